// round 2
// baseline (speedup 1.0000x reference)
#include <cuda_runtime.h>

#define H    32
#define NMAX 100000
#define EMAX 3200000
#define NL   3

// ---- scratch (static; no allocation allowed) ----
__device__ float  d_T[NMAX * H];      // T = node_in @ W_msg[:34]
__device__ float  d_h[NMAX * H];      // hidden state
__device__ float  d_pool[H];          // column sums of h
__device__ float  d_g[H];             // global supernode state
__device__ int    d_cnt[NMAX];        // histogram, then scatter cursor
__device__ int    d_tmp[NMAX];        // block-local inclusive scan
__device__ int    d_rowptr[NMAX + 1]; // CSR row pointers (by receiver)
__device__ int    d_bsum[1024];
__device__ int    d_boff[1024];
__device__ float4 d_pay[EMAX];        // {sender_bits, mask, ef0, ef1}
__device__ float2 d_pay2[EMAX];       // {ef2, ef3}

// ---------------------------------------------------------------------------
// init: V[:,0]=1,V[:,1]=0 ; h = PQ @ W_in + b_in ; g=0 ; cnt=0
// ---------------------------------------------------------------------------
__global__ void init_kernel(const float* __restrict__ PQ,
                            const float* __restrict__ Win,
                            const float* __restrict__ bin,
                            float* __restrict__ V, int N) {
    int gid = blockIdx.x * blockDim.x + threadIdx.x;
    if (gid < H) d_g[gid] = 0.f;
    if (gid < N) d_cnt[gid] = 0;
    if (gid < N * 2) V[gid] = (gid & 1) ? 0.f : 1.f;
    if (gid >= N * H) return;
    int i = gid >> 5, j = gid & 31;
    float p = __ldg(&PQ[i * 2]);
    float q = __ldg(&PQ[i * 2 + 1]);
    d_h[gid] = p * __ldg(&Win[j]) + q * __ldg(&Win[H + j]) + __ldg(&bin[j]);
}

// ---------------------------------------------------------------------------
// CSR build: histogram -> scan -> scatter
// ---------------------------------------------------------------------------
__global__ void hist_kernel(const int* __restrict__ recv, int E) {
    int e = blockIdx.x * blockDim.x + threadIdx.x;
    if (e < E) atomicAdd(&d_cnt[recv[e]], 1);
}

__global__ void scan1_kernel(int N) {
    __shared__ int sm[1024];
    int tid = threadIdx.x;
    int i = blockIdx.x * 1024 + tid;
    int v = (i < N) ? d_cnt[i] : 0;
    sm[tid] = v;
    __syncthreads();
#pragma unroll
    for (int off = 1; off < 1024; off <<= 1) {
        int t = (tid >= off) ? sm[tid - off] : 0;
        __syncthreads();
        sm[tid] += t;
        __syncthreads();
    }
    if (i < N) d_tmp[i] = sm[tid];
    if (tid == 1023) d_bsum[blockIdx.x] = sm[1023];
}

__global__ void scan2_kernel(int nb) {
    __shared__ int sm[1024];
    int tid = threadIdx.x;
    int v = (tid < nb) ? d_bsum[tid] : 0;
    sm[tid] = v;
    __syncthreads();
#pragma unroll
    for (int off = 1; off < 1024; off <<= 1) {
        int t = (tid >= off) ? sm[tid - off] : 0;
        __syncthreads();
        sm[tid] += t;
        __syncthreads();
    }
    d_boff[tid] = sm[tid] - v;   // exclusive
}

__global__ void scan3_kernel(int N) {
    int i = blockIdx.x * blockDim.x + threadIdx.x;
    if (i == 0) d_rowptr[0] = 0;
    if (i >= N) return;
    int incl = d_tmp[i] + d_boff[i >> 10];
    d_rowptr[i + 1] = incl;
    d_cnt[i] = incl - d_cnt[i];  // exclusive prefix -> scatter cursor
}

__global__ void scatter_kernel(const int*   __restrict__ send,
                               const int*   __restrict__ recv,
                               const float* __restrict__ ef,
                               const float* __restrict__ mask, int E) {
    int e = blockIdx.x * blockDim.x + threadIdx.x;
    if (e >= E) return;
    int r = recv[e];
    int pos = atomicAdd(&d_cnt[r], 1);
    float4 f = __ldg((const float4*)ef + e);
    d_pay[pos]  = make_float4(__int_as_float(__ldg(&send[e])), __ldg(&mask[e]), f.x, f.y);
    d_pay2[pos] = make_float2(f.z, f.w);
}

// ---------------------------------------------------------------------------
// prep: T[i][j] = [V_i(2), h_i(32)] . W_msg[l][0:34][j] ; zero pool
// ---------------------------------------------------------------------------
__global__ void prep_kernel(const float* __restrict__ V,
                            const float* __restrict__ Wmsg, int N) {
    __shared__ float Ws[34 * H];
    __shared__ float hs[8][H];
    for (int t = threadIdx.x; t < 34 * H; t += blockDim.x) Ws[t] = Wmsg[t];
    __syncthreads();

    int gid = blockIdx.x * blockDim.x + threadIdx.x;
    if (gid < H) d_pool[gid] = 0.f;
    if (gid >= N * H) return;
    int i = gid >> 5, j = gid & 31, w = threadIdx.x >> 5;

    hs[w][j] = d_h[gid];
    __syncwarp();

    float acc = __ldg(&V[i * 2]) * Ws[j] + __ldg(&V[i * 2 + 1]) * Ws[H + j];
#pragma unroll
    for (int k = 0; k < H; k++) acc += hs[w][k] * Ws[(2 + k) * H + j];
    d_T[gid] = acc;
}

// ---------------------------------------------------------------------------
// agg: h[r] = relu( sum_{e->r} mask*(T[s] + EF@W_ef + b) ) ; pool += colsums
// warp = node, lane = column. CSR gather, no atomics in hot loop.
// ---------------------------------------------------------------------------
__global__ void agg_kernel(const float* __restrict__ Wmsg,
                           const float* __restrict__ bmsg,
                           int N, int totalWarps) {
    __shared__ float psum[8][H];
    int j = threadIdx.x & 31;
    int w = threadIdx.x >> 5;

    float w0 = __ldg(&Wmsg[34 * H + j]);
    float w1 = __ldg(&Wmsg[35 * H + j]);
    float w2 = __ldg(&Wmsg[36 * H + j]);
    float w3 = __ldg(&Wmsg[37 * H + j]);
    float bj = __ldg(&bmsg[j]);

    float colsum = 0.f;
    for (int node = blockIdx.x * 8 + w; node < N; node += totalWarps) {
        int beg = d_rowptr[node], end = d_rowptr[node + 1];
        float acc = 0.f;
        int k = beg;
        for (; k + 4 <= end; k += 4) {
            float4 a0 = d_pay[k],     a1 = d_pay[k + 1];
            float4 a2 = d_pay[k + 2], a3 = d_pay[k + 3];
            float2 q0 = d_pay2[k],     q1 = d_pay2[k + 1];
            float2 q2 = d_pay2[k + 2], q3 = d_pay2[k + 3];
            float t0 = d_T[__float_as_int(a0.x) * H + j];
            float t1 = d_T[__float_as_int(a1.x) * H + j];
            float t2 = d_T[__float_as_int(a2.x) * H + j];
            float t3 = d_T[__float_as_int(a3.x) * H + j];
            acc += a0.y * (t0 + bj + a0.z * w0 + a0.w * w1 + q0.x * w2 + q0.y * w3);
            acc += a1.y * (t1 + bj + a1.z * w0 + a1.w * w1 + q1.x * w2 + q1.y * w3);
            acc += a2.y * (t2 + bj + a2.z * w0 + a2.w * w1 + q2.x * w2 + q2.y * w3);
            acc += a3.y * (t3 + bj + a3.z * w0 + a3.w * w1 + q3.x * w2 + q3.y * w3);
        }
        for (; k < end; k++) {
            float4 a = d_pay[k];
            float2 q = d_pay2[k];
            float t = d_T[__float_as_int(a.x) * H + j];
            acc += a.y * (t + bj + a.z * w0 + a.w * w1 + q.x * w2 + q.y * w3);
        }
        float hv = fmaxf(acc, 0.f);
        d_h[node * H + j] = hv;
        colsum += hv;
    }
    psum[w][j] = colsum;
    __syncthreads();
    if (threadIdx.x < H) {
        float s = 0.f;
#pragma unroll
        for (int q = 0; q < 8; q++) s += psum[q][j];
        atomicAdd(&d_pool[j], s);
    }
}

// ---------------------------------------------------------------------------
// global node: g = relu([g, mean(h)] @ W_g + b_g)
// ---------------------------------------------------------------------------
__global__ void g_kernel(const float* __restrict__ Wg,
                         const float* __restrict__ bg, float invN) {
    __shared__ float gin[2 * H];
    int t = threadIdx.x;
    gin[t]     = d_g[t];
    gin[H + t] = d_pool[t] * invN;
    __syncthreads();
    float acc = bg[t];
#pragma unroll
    for (int k = 0; k < 2 * H; k++) acc += gin[k] * Wg[k * H + t];
    d_g[t] = fmaxf(acc, 0.f);
}

// ---------------------------------------------------------------------------
// node update: u = relu([h, g] @ W_n + b_n) ; V += u @ W_out + b_out ; h = u
// ---------------------------------------------------------------------------
__global__ void node_kernel(const float* __restrict__ Wn,
                            const float* __restrict__ bn,
                            const float* __restrict__ Wout,
                            const float* __restrict__ bout,
                            float* __restrict__ V, int N) {
    __shared__ float Ws[2 * H * H];
    __shared__ float gs[H];
    __shared__ float hs[8][H];
    for (int t = threadIdx.x; t < 2 * H * H; t += blockDim.x) Ws[t] = Wn[t];
    if (threadIdx.x < H) gs[threadIdx.x] = d_g[threadIdx.x];
    __syncthreads();

    int w = threadIdx.x >> 5, j = threadIdx.x & 31;
    int i = blockIdx.x * 8 + w;
    if (i >= N) return;

    hs[w][j] = d_h[i * H + j];
    __syncwarp();

    float acc = bn[j];
#pragma unroll
    for (int k = 0; k < H; k++) acc += hs[w][k] * Ws[k * H + j];
#pragma unroll
    for (int k = 0; k < H; k++) acc += gs[k] * Ws[(H + k) * H + j];
    float u = fmaxf(acc, 0.f);
    d_h[i * H + j] = u;

    float v0 = u * __ldg(&Wout[j * 2]);
    float v1 = u * __ldg(&Wout[j * 2 + 1]);
#pragma unroll
    for (int off = 16; off; off >>= 1) {
        v0 += __shfl_xor_sync(0xffffffffu, v0, off);
        v1 += __shfl_xor_sync(0xffffffffu, v1, off);
    }
    if (j == 0) {
        V[i * 2]     += v0 + __ldg(&bout[0]);
        V[i * 2 + 1] += v1 + __ldg(&bout[1]);
    }
}

// ---------------------------------------------------------------------------
extern "C" void kernel_launch(void* const* d_in, const int* in_sizes, int n_in,
                              void* d_out, int out_size) {
    const float* PQ        = (const float*)d_in[0];
    const int*   senders   = (const int*)  d_in[1];
    const int*   receivers = (const int*)  d_in[2];
    const float* ef        = (const float*)d_in[3];
    const float* mask      = (const float*)d_in[4];
    const float* Win       = (const float*)d_in[5];
    const float* bin       = (const float*)d_in[6];
    const float* Wmsg      = (const float*)d_in[7];
    const float* bmsg      = (const float*)d_in[8];
    const float* Wg        = (const float*)d_in[9];
    const float* bg        = (const float*)d_in[10];
    const float* Wn        = (const float*)d_in[11];
    const float* bn        = (const float*)d_in[12];
    const float* Wout      = (const float*)d_in[13];
    const float* bout      = (const float*)d_in[14];
    float* V = (float*)d_out;

    int N = in_sizes[0] / 2;
    int E = in_sizes[1];

    int nb_nh = (N * H + 255) / 256;
    int nb_e  = (E + 255) / 256;
    int nb_sc = (N + 1023) / 1024;

    init_kernel<<<nb_nh, 256>>>(PQ, Win, bin, V, N);
    hist_kernel<<<nb_e, 256>>>(receivers, E);
    scan1_kernel<<<nb_sc, 1024>>>(N);
    scan2_kernel<<<1, 1024>>>(nb_sc);
    scan3_kernel<<<(N + 255) / 256, 256>>>(N);
    scatter_kernel<<<nb_e, 256>>>(senders, receivers, ef, mask, E);

    const int AGG_BLOCKS = 1184;  // 8 per SM
    for (int l = 0; l < NL; l++) {
        prep_kernel<<<nb_nh, 256>>>(V, Wmsg + l * 38 * H, N);
        agg_kernel<<<AGG_BLOCKS, 256>>>(Wmsg + l * 38 * H, bmsg + l * H,
                                        N, AGG_BLOCKS * 8);
        g_kernel<<<1, 32>>>(Wg + l * 2 * H * H, bg + l * H, 1.0f / (float)N);
        node_kernel<<<(N + 7) / 8, 256>>>(Wn + l * 2 * H * H, bn + l * H,
                                          Wout + l * H * 2, bout + l * 2, V, N);
    }
}

// round 4
// speedup vs baseline: 1.3143x; 1.3143x over previous
#include <cuda_runtime.h>

#define H    32
#define NMAX 100000
#define EMAX 3200000
#define PMAX (EMAX + 4 * NMAX)
#define NL   3

// ---- scratch (static; no allocation allowed) ----
__device__ float  d_T[NMAX * H];       // T = node_in @ W_msg[:34]
__device__ float  d_h[NMAX * H];       // hidden state
__device__ float  d_pool[H];           // column sums of h
__device__ float  d_g[H];              // global supernode state
__device__ int    d_cnt[NMAX];         // real degree -> scatter cursor
__device__ int    d_tmp[NMAX];         // block-local inclusive scan (padded)
__device__ int    d_rowptr[NMAX + 1];  // padded CSR row pointers (by receiver)
__device__ int    d_bsum[1024];
__device__ int    d_boff[1024];
__device__ __align__(16) float2 d_pay[PMAX];  // {sender_bits, mask}; pad slots stay 0
__device__ float4 d_payef[PMAX];       // edge features (CSR order); pad slots stay 0
__device__ float4 d_aef[NMAX];         // sum mask*EF per receiver
__device__ float  d_acnt[NMAX];        // sum mask per receiver

// ---------------------------------------------------------------------------
// init: V[:,0]=1,V[:,1]=0 ; h = PQ @ W_in + b_in ; g=0 ; cnt=0
// ---------------------------------------------------------------------------
__global__ void init_kernel(const float* __restrict__ PQ,
                            const float* __restrict__ Win,
                            const float* __restrict__ bin,
                            float* __restrict__ V, int N) {
    int gid = blockIdx.x * blockDim.x + threadIdx.x;
    if (gid < H) d_g[gid] = 0.f;
    if (gid < N) d_cnt[gid] = 0;
    if (gid < N * 2) V[gid] = (gid & 1) ? 0.f : 1.f;
    if (gid >= N * H) return;
    int i = gid >> 5, j = gid & 31;
    float p = __ldg(&PQ[i * 2]);
    float q = __ldg(&PQ[i * 2 + 1]);
    d_h[gid] = p * __ldg(&Win[j]) + q * __ldg(&Win[H + j]) + __ldg(&bin[j]);
}

// ---------------------------------------------------------------------------
// CSR build: histogram -> scan (padded to 4) -> scatter
// ---------------------------------------------------------------------------
__global__ void hist_kernel(const int* __restrict__ recv, int E) {
    int e = blockIdx.x * blockDim.x + threadIdx.x;
    if (e < E) atomicAdd(&d_cnt[__ldg(&recv[e])], 1);
}

__global__ void scan1_kernel(int N) {
    __shared__ int sm[1024];
    int tid = threadIdx.x;
    int i = blockIdx.x * 1024 + tid;
    int v = (i < N) ? ((d_cnt[i] + 3) & ~3) : 0;   // padded degree
    sm[tid] = v;
    __syncthreads();
#pragma unroll
    for (int off = 1; off < 1024; off <<= 1) {
        int t = (tid >= off) ? sm[tid - off] : 0;
        __syncthreads();
        sm[tid] += t;
        __syncthreads();
    }
    if (i < N) d_tmp[i] = sm[tid];
    if (tid == 1023) d_bsum[blockIdx.x] = sm[1023];
}

__global__ void scan2_kernel(int nb) {
    __shared__ int sm[1024];
    int tid = threadIdx.x;
    int v = (tid < nb) ? d_bsum[tid] : 0;
    sm[tid] = v;
    __syncthreads();
#pragma unroll
    for (int off = 1; off < 1024; off <<= 1) {
        int t = (tid >= off) ? sm[tid - off] : 0;
        __syncthreads();
        sm[tid] += t;
        __syncthreads();
    }
    d_boff[tid] = sm[tid] - v;   // exclusive
}

__global__ void scan3_kernel(int N) {
    int i = blockIdx.x * blockDim.x + threadIdx.x;
    if (i == 0) d_rowptr[0] = 0;
    if (i >= N) return;
    int real = d_cnt[i];
    int pad  = (real + 3) & ~3;
    int incl = d_tmp[i] + d_boff[i >> 10];  // inclusive padded prefix
    d_rowptr[i + 1] = incl;
    d_cnt[i] = incl - pad;                  // start cursor
}

__global__ void scatter_kernel(const int*   __restrict__ send,
                               const int*   __restrict__ recv,
                               const float* __restrict__ ef,
                               const float* __restrict__ mask, int E) {
    int e = blockIdx.x * blockDim.x + threadIdx.x;
    if (e >= E) return;
    int r = __ldg(&recv[e]);
    int pos = atomicAdd(&d_cnt[r], 1);
    d_pay[pos]   = make_float2(__int_as_float(__ldg(&send[e])), __ldg(&mask[e]));
    d_payef[pos] = __ldg((const float4*)ef + e);
}

// ---------------------------------------------------------------------------
// aef: AEF[r] = sum mask*EF ; acnt[r] = sum mask   (once; layer-independent)
// warp per node
// ---------------------------------------------------------------------------
__global__ void aef_kernel(int N) {
    int gid = blockIdx.x * blockDim.x + threadIdx.x;
    int node = gid >> 5, lane = gid & 31;
    if (node >= N) return;
    int beg = d_rowptr[node], end = d_rowptr[node + 1];
    float4 a = make_float4(0.f, 0.f, 0.f, 0.f);
    float c = 0.f;
    for (int k = beg + lane; k < end; k += 32) {
        float  mk = d_pay[k].y;       // pad slots: 0
        float4 f  = d_payef[k];       // pad slots: 0
        a.x += mk * f.x; a.y += mk * f.y;
        a.z += mk * f.z; a.w += mk * f.w;
        c += mk;
    }
#pragma unroll
    for (int off = 16; off; off >>= 1) {
        a.x += __shfl_xor_sync(0xffffffffu, a.x, off);
        a.y += __shfl_xor_sync(0xffffffffu, a.y, off);
        a.z += __shfl_xor_sync(0xffffffffu, a.z, off);
        a.w += __shfl_xor_sync(0xffffffffu, a.w, off);
        c   += __shfl_xor_sync(0xffffffffu, c, off);
    }
    if (lane == 0) { d_aef[node] = a; d_acnt[node] = c; }
}

// ---------------------------------------------------------------------------
// prep: T[i][j] = [V_i(2), h_i(32)] . W_msg[l][0:34][j] ; zero pool
// ---------------------------------------------------------------------------
__global__ void __launch_bounds__(1024)
prep_kernel(const float* __restrict__ V, const float* __restrict__ Wmsg, int N) {
    __shared__ float Ws[34 * H];
    __shared__ float hs[32][H];
    for (int t = threadIdx.x; t < 34 * H; t += blockDim.x) Ws[t] = Wmsg[t];
    __syncthreads();

    int gid = blockIdx.x * blockDim.x + threadIdx.x;
    if (gid < H) d_pool[gid] = 0.f;
    if (gid >= N * H) return;
    int i = gid >> 5, j = gid & 31, w = threadIdx.x >> 5;

    hs[w][j] = d_h[gid];
    __syncwarp();

    float acc = __ldg(&V[i * 2]) * Ws[j] + __ldg(&V[i * 2 + 1]) * Ws[H + j];
#pragma unroll
    for (int k = 0; k < H; k++) acc += hs[w][k] * Ws[(2 + k) * H + j];
    d_T[gid] = acc;
}

// ---------------------------------------------------------------------------
// agg: h[r] = relu( sum mask*T[s]  + AEF[r]@W_ef + acnt[r]*b ) ; pool += colsums
// 4 nodes per warp, 8 lanes (float4 cols) per node. Padded CSR: deg % 4 == 0.
// ---------------------------------------------------------------------------
__global__ void agg_kernel(const float* __restrict__ Wmsg,
                           const float* __restrict__ bmsg, int N) {
    int lane = threadIdx.x & 31;
    int sub  = lane >> 3;
    int col  = (lane & 7) * 4;
    int warp = threadIdx.x >> 5;
    int node = blockIdx.x * 32 + warp * 4 + sub;

    float4 w0 = *(const float4*)&Wmsg[34 * H + col];
    float4 w1 = *(const float4*)&Wmsg[35 * H + col];
    float4 w2 = *(const float4*)&Wmsg[36 * H + col];
    float4 w3 = *(const float4*)&Wmsg[37 * H + col];
    float4 bb = *(const float4*)&bmsg[col];

    float4 acc = make_float4(0.f, 0.f, 0.f, 0.f);
    if (node < N) {
        int beg = d_rowptr[node], end = d_rowptr[node + 1];
        for (int k = beg; k < end; k += 4) {
            float4 pA = *(const float4*)&d_pay[k];      // edges k, k+1
            float4 pB = *(const float4*)&d_pay[k + 2];  // edges k+2, k+3
            float4 t0 = *(const float4*)&d_T[__float_as_int(pA.x) * H + col];
            float4 t1 = *(const float4*)&d_T[__float_as_int(pA.z) * H + col];
            float4 t2 = *(const float4*)&d_T[__float_as_int(pB.x) * H + col];
            float4 t3 = *(const float4*)&d_T[__float_as_int(pB.z) * H + col];
            acc.x = fmaf(pA.y, t0.x, acc.x); acc.y = fmaf(pA.y, t0.y, acc.y);
            acc.z = fmaf(pA.y, t0.z, acc.z); acc.w = fmaf(pA.y, t0.w, acc.w);
            acc.x = fmaf(pA.w, t1.x, acc.x); acc.y = fmaf(pA.w, t1.y, acc.y);
            acc.z = fmaf(pA.w, t1.z, acc.z); acc.w = fmaf(pA.w, t1.w, acc.w);
            acc.x = fmaf(pB.y, t2.x, acc.x); acc.y = fmaf(pB.y, t2.y, acc.y);
            acc.z = fmaf(pB.y, t2.z, acc.z); acc.w = fmaf(pB.y, t2.w, acc.w);
            acc.x = fmaf(pB.w, t3.x, acc.x); acc.y = fmaf(pB.w, t3.y, acc.y);
            acc.z = fmaf(pB.w, t3.z, acc.z); acc.w = fmaf(pB.w, t3.w, acc.w);
        }
        float4 aef = d_aef[node];
        float  cnt = d_acnt[node];
        acc.x += aef.x * w0.x + aef.y * w1.x + aef.z * w2.x + aef.w * w3.x + cnt * bb.x;
        acc.y += aef.x * w0.y + aef.y * w1.y + aef.z * w2.y + aef.w * w3.y + cnt * bb.y;
        acc.z += aef.x * w0.z + aef.y * w1.z + aef.z * w2.z + aef.w * w3.z + cnt * bb.z;
        acc.w += aef.x * w0.w + aef.y * w1.w + aef.z * w2.w + aef.w * w3.w + cnt * bb.w;
        acc.x = fmaxf(acc.x, 0.f); acc.y = fmaxf(acc.y, 0.f);
        acc.z = fmaxf(acc.z, 0.f); acc.w = fmaxf(acc.w, 0.f);
        *(float4*)&d_h[node * H + col] = acc;
    }
    // pool reduction: sum h columns over block's nodes
#pragma unroll
    for (int off = 8; off <= 16; off <<= 1) {
        acc.x += __shfl_xor_sync(0xffffffffu, acc.x, off);
        acc.y += __shfl_xor_sync(0xffffffffu, acc.y, off);
        acc.z += __shfl_xor_sync(0xffffffffu, acc.z, off);
        acc.w += __shfl_xor_sync(0xffffffffu, acc.w, off);
    }
    __shared__ float4 wsum[8][8];
    if (lane < 8) wsum[warp][lane] = acc;
    __syncthreads();
    if (threadIdx.x < 8) {
        float4 s = make_float4(0.f, 0.f, 0.f, 0.f);
#pragma unroll
        for (int w = 0; w < 8; w++) {
            float4 v = wsum[w][threadIdx.x];
            s.x += v.x; s.y += v.y; s.z += v.z; s.w += v.w;
        }
        float* dst = &d_pool[threadIdx.x * 4];
        asm volatile("red.global.add.v4.f32 [%0], {%1,%2,%3,%4};"
                     :: "l"(dst), "f"(s.x), "f"(s.y), "f"(s.z), "f"(s.w) : "memory");
    }
}

// ---------------------------------------------------------------------------
// global node: g = relu([g, mean(h)] @ W_g + b_g)
// ---------------------------------------------------------------------------
__global__ void g_kernel(const float* __restrict__ Wg,
                         const float* __restrict__ bg, float invN) {
    __shared__ float gin[2 * H];
    int t = threadIdx.x;
    gin[t]     = d_g[t];
    gin[H + t] = d_pool[t] * invN;
    __syncthreads();
    float acc = bg[t];
#pragma unroll
    for (int k = 0; k < 2 * H; k++) acc += gin[k] * Wg[k * H + t];
    d_g[t] = fmaxf(acc, 0.f);
}

// ---------------------------------------------------------------------------
// node update: u = relu([h, g] @ W_n + b_n) ; V += u @ W_out + b_out ; h = u
// ---------------------------------------------------------------------------
__global__ void __launch_bounds__(1024)
node_kernel(const float* __restrict__ Wn, const float* __restrict__ bn,
            const float* __restrict__ Wout, const float* __restrict__ bout,
            float* __restrict__ V, int N) {
    __shared__ float Ws[2 * H * H];
    __shared__ float gs[H];
    __shared__ float hs[32][H];
    for (int t = threadIdx.x; t < 2 * H * H; t += blockDim.x) Ws[t] = Wn[t];
    if (threadIdx.x < H) gs[threadIdx.x] = d_g[threadIdx.x];
    __syncthreads();

    int w = threadIdx.x >> 5, j = threadIdx.x & 31;
    int i = blockIdx.x * 32 + w;
    if (i >= N) return;

    hs[w][j] = d_h[i * H + j];
    __syncwarp();

    float acc = bn[j];
#pragma unroll
    for (int k = 0; k < H; k++) acc += hs[w][k] * Ws[k * H + j];
#pragma unroll
    for (int k = 0; k < H; k++) acc += gs[k] * Ws[(H + k) * H + j];
    float u = fmaxf(acc, 0.f);
    d_h[i * H + j] = u;

    float v0 = u * __ldg(&Wout[j * 2]);
    float v1 = u * __ldg(&Wout[j * 2 + 1]);
#pragma unroll
    for (int off = 16; off; off >>= 1) {
        v0 += __shfl_xor_sync(0xffffffffu, v0, off);
        v1 += __shfl_xor_sync(0xffffffffu, v1, off);
    }
    if (j == 0) {
        V[i * 2]     += v0 + __ldg(&bout[0]);
        V[i * 2 + 1] += v1 + __ldg(&bout[1]);
    }
}

// ---------------------------------------------------------------------------
extern "C" void kernel_launch(void* const* d_in, const int* in_sizes, int n_in,
                              void* d_out, int out_size) {
    const float* PQ        = (const float*)d_in[0];
    const int*   senders   = (const int*)  d_in[1];
    const int*   receivers = (const int*)  d_in[2];
    const float* ef        = (const float*)d_in[3];
    const float* mask      = (const float*)d_in[4];
    const float* Win       = (const float*)d_in[5];
    const float* bin       = (const float*)d_in[6];
    const float* Wmsg      = (const float*)d_in[7];
    const float* bmsg      = (const float*)d_in[8];
    const float* Wg        = (const float*)d_in[9];
    const float* bg        = (const float*)d_in[10];
    const float* Wn        = (const float*)d_in[11];
    const float* bn        = (const float*)d_in[12];
    const float* Wout      = (const float*)d_in[13];
    const float* bout      = (const float*)d_in[14];
    float* V = (float*)d_out;

    int N = in_sizes[0] / 2;
    int E = in_sizes[1];

    int nb_nh = (N * H + 255) / 256;
    int nb_e  = (E + 255) / 256;
    int nb_sc = (N + 1023) / 1024;
    int nb_n32 = (N + 31) / 32;

    init_kernel<<<nb_nh, 256>>>(PQ, Win, bin, V, N);
    hist_kernel<<<nb_e, 256>>>(receivers, E);
    scan1_kernel<<<nb_sc, 1024>>>(N);
    scan2_kernel<<<1, 1024>>>(nb_sc);
    scan3_kernel<<<(N + 255) / 256, 256>>>(N);
    scatter_kernel<<<nb_e, 256>>>(senders, receivers, ef, mask, E);
    aef_kernel<<<nb_nh, 256>>>(N);

    for (int l = 0; l < NL; l++) {
        prep_kernel<<<(N * H + 1023) / 1024, 1024>>>(V, Wmsg + l * 38 * H, N);
        agg_kernel<<<nb_n32, 256>>>(Wmsg + l * 38 * H, bmsg + l * H, N);
        g_kernel<<<1, 32>>>(Wg + l * 2 * H * H, bg + l * H, 1.0f / (float)N);
        node_kernel<<<nb_n32, 1024>>>(Wn + l * 2 * H * H, bn + l * H,
                                      Wout + l * H * 2, bout + l * 2, V, N);
    }
}

// round 7
// speedup vs baseline: 1.6098x; 1.2248x over previous
#include <cuda_runtime.h>
#include <cuda_fp16.h>

#define H    32
#define NMAX 100000
#define EMAX 3200000
#define PMAX (EMAX + 4 * NMAX)
#define NL   3

// ---- scratch (static; no allocation allowed) ----
__device__ __half d_Th[NMAX * H];      // T = node_in @ W_msg[:34]  (fp16)
__device__ float  d_h[NMAX * H];       // hidden state
__device__ float  d_pool[H];           // column sums of h
__device__ float  d_g[H];              // global supernode state
__device__ int    d_cnt[NMAX];         // degree -> scatter cursor
__device__ int    d_tmp[NMAX];         // block-local inclusive scan (padded)
__device__ int    d_rowptr[NMAX + 1];  // padded CSR row pointers (by receiver)
__device__ int    d_bsum[1024];
__device__ int    d_boff[1024];
__device__ __align__(16) float2 d_pay[PMAX];  // {sender_bits, mask}; pad slots stay 0
__device__ float4 d_aef[NMAX];         // sum mask*EF per receiver
__device__ float  d_acnt[NMAX];        // sum mask per receiver

// ---------------------------------------------------------------------------
// init: V=(1,0) ; h = PQ @ W_in + b_in ; T0 = [1,0,h] @ W_msg[0][:34]
// zero g/pool/cnt/aef/acnt. warp = node, lane = column.
// ---------------------------------------------------------------------------
__global__ void init_kernel(const float* __restrict__ PQ,
                            const float* __restrict__ Win,
                            const float* __restrict__ bin,
                            const float* __restrict__ Wmsg0,
                            float* __restrict__ V, int N) {
    __shared__ float Ws[34 * H];
    __shared__ float hs[8][H];
    for (int t = threadIdx.x; t < 34 * H; t += blockDim.x) Ws[t] = Wmsg0[t];

    int gid = blockIdx.x * blockDim.x + threadIdx.x;
    if (gid < H) { d_g[gid] = 0.f; d_pool[gid] = 0.f; }
    if (gid < N) {
        d_cnt[gid] = 0; d_acnt[gid] = 0.f;
        d_aef[gid] = make_float4(0.f, 0.f, 0.f, 0.f);
    }
    if (gid < N * 2) V[gid] = (gid & 1) ? 0.f : 1.f;

    bool active = gid < N * H;
    int i = gid >> 5, j = gid & 31, w = threadIdx.x >> 5;
    float h = 0.f;
    if (active) {
        float p = __ldg(&PQ[i * 2]);
        float q = __ldg(&PQ[i * 2 + 1]);
        h = p * __ldg(&Win[j]) + q * __ldg(&Win[H + j]) + __ldg(&bin[j]);
        hs[w][j] = h;
    }
    __syncthreads();
    if (active) {
        d_h[gid] = h;
        float acc = Ws[j];                 // V = (1, 0)
#pragma unroll
        for (int k = 0; k < H; k++) acc += hs[w][k] * Ws[(2 + k) * H + j];
        d_Th[gid] = __float2half_rn(acc);
    }
}

// ---------------------------------------------------------------------------
// CSR build: histogram -> scan (padded to 4) -> scatter(+AEF)
// ---------------------------------------------------------------------------
__global__ void hist_kernel(const int* __restrict__ recv, int E) {
    int e = blockIdx.x * blockDim.x + threadIdx.x;
    if (e < E) atomicAdd(&d_cnt[__ldg(&recv[e])], 1);
}

__global__ void scan1_kernel(int N) {
    __shared__ int sm[1024];
    int tid = threadIdx.x;
    int i = blockIdx.x * 1024 + tid;
    int v = (i < N) ? ((d_cnt[i] + 3) & ~3) : 0;   // padded degree
    sm[tid] = v;
    __syncthreads();
#pragma unroll
    for (int off = 1; off < 1024; off <<= 1) {
        int t = (tid >= off) ? sm[tid - off] : 0;
        __syncthreads();
        sm[tid] += t;
        __syncthreads();
    }
    if (i < N) d_tmp[i] = sm[tid];
    if (tid == 1023) d_bsum[blockIdx.x] = sm[1023];
}

__global__ void scan2_kernel(int nb) {
    __shared__ int sm[1024];
    int tid = threadIdx.x;
    int v = (tid < nb) ? d_bsum[tid] : 0;
    sm[tid] = v;
    __syncthreads();
#pragma unroll
    for (int off = 1; off < 1024; off <<= 1) {
        int t = (tid >= off) ? sm[tid - off] : 0;
        __syncthreads();
        sm[tid] += t;
        __syncthreads();
    }
    d_boff[tid] = sm[tid] - v;   // exclusive
}

__global__ void scan3_kernel(int N) {
    int i = blockIdx.x * blockDim.x + threadIdx.x;
    if (i == 0) d_rowptr[0] = 0;
    if (i >= N) return;
    int real = d_cnt[i];
    int pad  = (real + 3) & ~3;
    int incl = d_tmp[i] + d_boff[i >> 10];  // inclusive padded prefix
    d_rowptr[i + 1] = incl;
    d_cnt[i] = incl - pad;                  // start cursor
}

__global__ void scatter_kernel(const int*   __restrict__ send,
                               const int*   __restrict__ recv,
                               const float* __restrict__ ef,
                               const float* __restrict__ mask, int E) {
    int e = blockIdx.x * blockDim.x + threadIdx.x;
    if (e >= E) return;
    int r = __ldg(&recv[e]);
    int pos = atomicAdd(&d_cnt[r], 1);
    float mk = __ldg(&mask[e]);
    d_pay[pos] = make_float2(__int_as_float(__ldg(&send[e])), mk);
    float4 f = __ldg((const float4*)ef + e);
    float4* dst = &d_aef[r];
    asm volatile("red.global.add.v4.f32 [%0], {%1,%2,%3,%4};"
                 :: "l"(dst), "f"(mk * f.x), "f"(mk * f.y),
                    "f"(mk * f.z), "f"(mk * f.w) : "memory");
    atomicAdd(&d_acnt[r], mk);
}

// ---------------------------------------------------------------------------
// agg: h[r] = relu( sum mask*T[s] + AEF[r]@W_ef + acnt[r]*b ) ; pool += colsums
// 4 nodes per warp, 8 lanes (4 cols, fp16) per node. Padded CSR: deg % 4 == 0.
// ---------------------------------------------------------------------------
__global__ void agg_kernel(const float* __restrict__ Wmsg,
                           const float* __restrict__ bmsg, int N) {
    int lane = threadIdx.x & 31;
    int sub  = lane >> 3;
    int col  = (lane & 7) * 4;
    int warp = threadIdx.x >> 5;
    int node = blockIdx.x * 32 + warp * 4 + sub;

    float4 w0 = *(const float4*)&Wmsg[34 * H + col];
    float4 w1 = *(const float4*)&Wmsg[35 * H + col];
    float4 w2 = *(const float4*)&Wmsg[36 * H + col];
    float4 w3 = *(const float4*)&Wmsg[37 * H + col];
    float4 bb = *(const float4*)&bmsg[col];

    float4 acc = make_float4(0.f, 0.f, 0.f, 0.f);
    if (node < N) {
        int beg = d_rowptr[node], end = d_rowptr[node + 1];
        for (int k = beg; k < end; k += 4) {
            float4 pA = *(const float4*)&d_pay[k];      // edges k, k+1
            float4 pB = *(const float4*)&d_pay[k + 2];  // edges k+2, k+3
            uint2 r0 = *(const uint2*)(d_Th + __float_as_int(pA.x) * H + col);
            uint2 r1 = *(const uint2*)(d_Th + __float_as_int(pA.z) * H + col);
            uint2 r2 = *(const uint2*)(d_Th + __float_as_int(pB.x) * H + col);
            uint2 r3 = *(const uint2*)(d_Th + __float_as_int(pB.z) * H + col);
            float2 l0 = __half22float2(*(__half2*)&r0.x), u0 = __half22float2(*(__half2*)&r0.y);
            float2 l1 = __half22float2(*(__half2*)&r1.x), u1 = __half22float2(*(__half2*)&r1.y);
            float2 l2 = __half22float2(*(__half2*)&r2.x), u2 = __half22float2(*(__half2*)&r2.y);
            float2 l3 = __half22float2(*(__half2*)&r3.x), u3 = __half22float2(*(__half2*)&r3.y);
            acc.x = fmaf(pA.y, l0.x, acc.x); acc.y = fmaf(pA.y, l0.y, acc.y);
            acc.z = fmaf(pA.y, u0.x, acc.z); acc.w = fmaf(pA.y, u0.y, acc.w);
            acc.x = fmaf(pA.w, l1.x, acc.x); acc.y = fmaf(pA.w, l1.y, acc.y);
            acc.z = fmaf(pA.w, u1.x, acc.z); acc.w = fmaf(pA.w, u1.y, acc.w);
            acc.x = fmaf(pB.y, l2.x, acc.x); acc.y = fmaf(pB.y, l2.y, acc.y);
            acc.z = fmaf(pB.y, u2.x, acc.z); acc.w = fmaf(pB.y, u2.y, acc.w);
            acc.x = fmaf(pB.w, l3.x, acc.x); acc.y = fmaf(pB.w, l3.y, acc.y);
            acc.z = fmaf(pB.w, u3.x, acc.z); acc.w = fmaf(pB.w, u3.y, acc.w);
        }
        float4 aef = d_aef[node];
        float  cnt = d_acnt[node];
        acc.x += aef.x * w0.x + aef.y * w1.x + aef.z * w2.x + aef.w * w3.x + cnt * bb.x;
        acc.y += aef.x * w0.y + aef.y * w1.y + aef.z * w2.y + aef.w * w3.y + cnt * bb.y;
        acc.z += aef.x * w0.z + aef.y * w1.z + aef.z * w2.z + aef.w * w3.z + cnt * bb.z;
        acc.w += aef.x * w0.w + aef.y * w1.w + aef.z * w2.w + aef.w * w3.w + cnt * bb.w;
        acc.x = fmaxf(acc.x, 0.f); acc.y = fmaxf(acc.y, 0.f);
        acc.z = fmaxf(acc.z, 0.f); acc.w = fmaxf(acc.w, 0.f);
        *(float4*)&d_h[node * H + col] = acc;
    }
    // pool reduction: sum h columns over block's nodes
#pragma unroll
    for (int off = 8; off <= 16; off <<= 1) {
        acc.x += __shfl_xor_sync(0xffffffffu, acc.x, off);
        acc.y += __shfl_xor_sync(0xffffffffu, acc.y, off);
        acc.z += __shfl_xor_sync(0xffffffffu, acc.z, off);
        acc.w += __shfl_xor_sync(0xffffffffu, acc.w, off);
    }
    __shared__ float4 wsum[8][8];
    if (lane < 8) wsum[warp][lane] = acc;
    __syncthreads();
    if (threadIdx.x < 8) {
        float4 s = make_float4(0.f, 0.f, 0.f, 0.f);
#pragma unroll
        for (int w = 0; w < 8; w++) {
            float4 v = wsum[w][threadIdx.x];
            s.x += v.x; s.y += v.y; s.z += v.z; s.w += v.w;
        }
        float* dst = &d_pool[threadIdx.x * 4];
        asm volatile("red.global.add.v4.f32 [%0], {%1,%2,%3,%4};"
                     :: "l"(dst), "f"(s.x), "f"(s.y), "f"(s.z), "f"(s.w) : "memory");
    }
}

// ---------------------------------------------------------------------------
// global node: g = relu([g, mean(h)] @ W_g + b_g) ; reset pool for next layer
// ---------------------------------------------------------------------------
__global__ void g_kernel(const float* __restrict__ Wg,
                         const float* __restrict__ bg, float invN) {
    __shared__ float gin[2 * H];
    int t = threadIdx.x;
    gin[t]     = d_g[t];
    gin[H + t] = d_pool[t] * invN;
    d_pool[t]  = 0.f;
    __syncthreads();
    float acc = bg[t];
#pragma unroll
    for (int k = 0; k < 2 * H; k++) acc += gin[k] * Wg[k * H + t];
    d_g[t] = fmaxf(acc, 0.f);
}

// ---------------------------------------------------------------------------
// node update: u = relu([h, g] @ W_n + b_n) ; V += u @ W_out + b_out ; h = u ;
// then T_next = [Vnew, u] @ W_msg[l+1][:34]   (fused next-layer prep)
// ---------------------------------------------------------------------------
__global__ void __launch_bounds__(1024)
node_kernel(const float* __restrict__ Wn, const float* __restrict__ bn,
            const float* __restrict__ Wout, const float* __restrict__ bout,
            const float* __restrict__ WmsgNext,   // nullptr on last layer
            float* __restrict__ V, int N) {
    __shared__ float Ws[2 * H * H];
    __shared__ float Wm[34 * H];
    __shared__ float gs[H];
    __shared__ float hs[32][H];
    for (int t = threadIdx.x; t < 2 * H * H; t += blockDim.x) Ws[t] = Wn[t];
    if (WmsgNext)
        for (int t = threadIdx.x; t < 34 * H; t += blockDim.x) Wm[t] = WmsgNext[t];
    if (threadIdx.x < H) gs[threadIdx.x] = d_g[threadIdx.x];
    __syncthreads();

    int w = threadIdx.x >> 5, j = threadIdx.x & 31;
    int i = blockIdx.x * 32 + w;
    if (i >= N) return;

    hs[w][j] = d_h[i * H + j];
    __syncwarp();

    float acc = bn[j];
#pragma unroll
    for (int k = 0; k < H; k++) acc += hs[w][k] * Ws[k * H + j];
#pragma unroll
    for (int k = 0; k < H; k++) acc += gs[k] * Ws[(H + k) * H + j];
    float u = fmaxf(acc, 0.f);
    d_h[i * H + j] = u;

    float v0 = u * __ldg(&Wout[j * 2]);
    float v1 = u * __ldg(&Wout[j * 2 + 1]);
#pragma unroll
    for (int off = 16; off; off >>= 1) {
        v0 += __shfl_xor_sync(0xffffffffu, v0, off);
        v1 += __shfl_xor_sync(0xffffffffu, v1, off);
    }
    float nv0 = __ldg(&V[i * 2])     + v0 + __ldg(&bout[0]);
    float nv1 = __ldg(&V[i * 2 + 1]) + v1 + __ldg(&bout[1]);
    if (j == 0) { V[i * 2] = nv0; V[i * 2 + 1] = nv1; }

    if (WmsgNext) {
        __syncwarp();
        hs[w][j] = u;
        __syncwarp();
        float t = nv0 * Wm[j] + nv1 * Wm[H + j];
#pragma unroll
        for (int k = 0; k < H; k++) t += hs[w][k] * Wm[(2 + k) * H + j];
        d_Th[i * H + j] = __float2half_rn(t);
    }
}

// ---------------------------------------------------------------------------
extern "C" void kernel_launch(void* const* d_in, const int* in_sizes, int n_in,
                              void* d_out, int out_size) {
    const float* PQ        = (const float*)d_in[0];
    const int*   senders   = (const int*)  d_in[1];
    const int*   receivers = (const int*)  d_in[2];
    const float* ef        = (const float*)d_in[3];
    const float* mask      = (const float*)d_in[4];
    const float* Win       = (const float*)d_in[5];
    const float* bin       = (const float*)d_in[6];
    const float* Wmsg      = (const float*)d_in[7];
    const float* bmsg      = (const float*)d_in[8];
    const float* Wg        = (const float*)d_in[9];
    const float* bg        = (const float*)d_in[10];
    const float* Wn        = (const float*)d_in[11];
    const float* bn        = (const float*)d_in[12];
    const float* Wout      = (const float*)d_in[13];
    const float* bout      = (const float*)d_in[14];
    float* V = (float*)d_out;

    int N = in_sizes[0] / 2;
    int E = in_sizes[1];

    int nb_nh = (N * H + 255) / 256;
    int nb_e  = (E + 255) / 256;
    int nb_sc = (N + 1023) / 1024;
    int nb_n32 = (N + 31) / 32;

    init_kernel<<<nb_nh, 256>>>(PQ, Win, bin, Wmsg, V, N);
    hist_kernel<<<nb_e, 256>>>(receivers, E);
    scan1_kernel<<<nb_sc, 1024>>>(N);
    scan2_kernel<<<1, 1024>>>(nb_sc);
    scan3_kernel<<<(N + 255) / 256, 256>>>(N);
    scatter_kernel<<<nb_e, 256>>>(senders, receivers, ef, mask, E);

    for (int l = 0; l < NL; l++) {
        agg_kernel<<<nb_n32, 256>>>(Wmsg + l * 38 * H, bmsg + l * H, N);
        g_kernel<<<1, 32>>>(Wg + l * 2 * H * H, bg + l * H, 1.0f / (float)N);
        const float* WmsgNext = (l + 1 < NL) ? (Wmsg + (l + 1) * 38 * H) : nullptr;
        node_kernel<<<nb_n32, 1024>>>(Wn + l * 2 * H * H, bn + l * H,
                                      Wout + l * H * 2, bout + l * 2,
                                      WmsgNext, V, N);
    }
}